// round 1
// baseline (speedup 1.0000x reference)
#include <cuda_runtime.h>

#define L    4096
#define DM   768
#define NH   12
#define HD   64
#define ATTN_SCALE 0.125f   // 1/sqrt(64)

// ---------------- scratch (no allocations allowed) ----------------
__device__ float g_Q[NH * L * HD];     // [h][i][d]
__device__ float g_K[NH * L * HD];
__device__ float g_V[NH * L * HD];
__device__ float g_attn[L * DM];       // [i][h*64+d]  token-major

// ---------------- tiled SGEMM: C[i,j] = sum_k X[i,k]*W[j,k] + b[j] ----------------
// BM=BN=64, BK=16, 256 threads, 4x4 microtile.

__global__ void __launch_bounds__(256)
qkv_proj_kernel(const float* __restrict__ xq, const float* __restrict__ xk, const float* __restrict__ xv,
                const float* __restrict__ wq, const float* __restrict__ wk, const float* __restrict__ wv,
                const float* __restrict__ bq, const float* __restrict__ bk, const float* __restrict__ bv)
{
    const int z = blockIdx.z;
    const float* __restrict__ X  = (z == 0) ? xq : (z == 1) ? xk : xv;
    const float* __restrict__ W  = (z == 0) ? wq : (z == 1) ? wk : wv;
    const float* __restrict__ Bb = (z == 0) ? bq : (z == 1) ? bk : bv;
    float* __restrict__ dst      = (z == 0) ? g_Q : (z == 1) ? g_K : g_V;

    __shared__ float As[16][64];
    __shared__ float Bs[16][64];

    const int tid  = threadIdx.x;
    const int i0   = blockIdx.x * 64;
    const int h    = blockIdx.y;          // BN==HD==64 -> one head per block column
    const int j0   = h * 64;
    const int lrow = tid >> 2;            // 0..63
    const int lk   = (tid & 3) * 4;       // 0,4,8,12
    const int ty   = tid >> 4;            // 0..15
    const int tx   = tid & 15;            // 0..15

    float acc[4][4] = {};

    for (int kt = 0; kt < DM; kt += 16) {
        const float4 a4 = *(const float4*)&X[(size_t)(i0 + lrow) * DM + kt + lk];
        const float4 b4 = *(const float4*)&W[(size_t)(j0 + lrow) * DM + kt + lk];
        As[lk + 0][lrow] = a4.x; As[lk + 1][lrow] = a4.y;
        As[lk + 2][lrow] = a4.z; As[lk + 3][lrow] = a4.w;
        Bs[lk + 0][lrow] = b4.x; Bs[lk + 1][lrow] = b4.y;
        Bs[lk + 2][lrow] = b4.z; Bs[lk + 3][lrow] = b4.w;
        __syncthreads();

#pragma unroll
        for (int k = 0; k < 16; ++k) {
            const float4 av = *(const float4*)&As[k][ty * 4];
            const float4 bv = *(const float4*)&Bs[k][tx * 4];
            const float a_[4] = {av.x, av.y, av.z, av.w};
            const float b_[4] = {bv.x, bv.y, bv.z, bv.w};
#pragma unroll
            for (int m = 0; m < 4; ++m)
#pragma unroll
                for (int n = 0; n < 4; ++n)
                    acc[m][n] = fmaf(a_[m], b_[n], acc[m][n]);
        }
        __syncthreads();
    }

    const float4 bias = *(const float4*)&Bb[j0 + tx * 4];
    const float bb[4] = {bias.x, bias.y, bias.z, bias.w};
#pragma unroll
    for (int m = 0; m < 4; ++m) {
        const int i = i0 + ty * 4 + m;
        float4 st;
        st.x = acc[m][0] + bb[0];
        st.y = acc[m][1] + bb[1];
        st.z = acc[m][2] + bb[2];
        st.w = acc[m][3] + bb[3];
        *(float4*)&dst[((size_t)h * L + i) * HD + tx * 4] = st;
    }
}

__global__ void __launch_bounds__(256)
out_proj_kernel(const float* __restrict__ W, const float* __restrict__ Bb,
                float* __restrict__ out)
{
    __shared__ float As[16][64];
    __shared__ float Bs[16][64];

    const int tid  = threadIdx.x;
    const int i0   = blockIdx.x * 64;
    const int j0   = blockIdx.y * 64;
    const int lrow = tid >> 2;
    const int lk   = (tid & 3) * 4;
    const int ty   = tid >> 4;
    const int tx   = tid & 15;

    float acc[4][4] = {};

    for (int kt = 0; kt < DM; kt += 16) {
        const float4 a4 = *(const float4*)&g_attn[(size_t)(i0 + lrow) * DM + kt + lk];
        const float4 b4 = *(const float4*)&W[(size_t)(j0 + lrow) * DM + kt + lk];
        As[lk + 0][lrow] = a4.x; As[lk + 1][lrow] = a4.y;
        As[lk + 2][lrow] = a4.z; As[lk + 3][lrow] = a4.w;
        Bs[lk + 0][lrow] = b4.x; Bs[lk + 1][lrow] = b4.y;
        Bs[lk + 2][lrow] = b4.z; Bs[lk + 3][lrow] = b4.w;
        __syncthreads();

#pragma unroll
        for (int k = 0; k < 16; ++k) {
            const float4 av = *(const float4*)&As[k][ty * 4];
            const float4 bv = *(const float4*)&Bs[k][tx * 4];
            const float a_[4] = {av.x, av.y, av.z, av.w};
            const float b_[4] = {bv.x, bv.y, bv.z, bv.w};
#pragma unroll
            for (int m = 0; m < 4; ++m)
#pragma unroll
                for (int n = 0; n < 4; ++n)
                    acc[m][n] = fmaf(a_[m], b_[n], acc[m][n]);
        }
        __syncthreads();
    }

    const float4 bias = *(const float4*)&Bb[j0 + tx * 4];
    const float bb[4] = {bias.x, bias.y, bias.z, bias.w};
#pragma unroll
    for (int m = 0; m < 4; ++m) {
        const int i = i0 + ty * 4 + m;
        float4 st;
        st.x = acc[m][0] + bb[0];
        st.y = acc[m][1] + bb[1];
        st.z = acc[m][2] + bb[2];
        st.w = acc[m][3] + bb[3];
        *(float4*)&out[(size_t)i * DM + j0 + tx * 4] = st;
    }
}

// ---------------- sliding-window attention ----------------
// One block per (64-query tile, head). Keys needed: [q0-64, q0+127] -> 192 rows.
// smem strides (floats), all multiples of 4 for float4 alignment:
#define QS_S 68
#define KS_S 196
#define VS_S 68
#define SS_S 68
#define ATT_SMEM_FLOATS (64 * QS_S + 64 * KS_S + 192 * VS_S + 192 * SS_S)
#define ATT_SMEM_BYTES  (ATT_SMEM_FLOATS * 4)

__global__ void __launch_bounds__(256)
attn_kernel()
{
    extern __shared__ float sm[];
    float* Qs = sm;                      // [d][q]  64 x QS_S
    float* Ks = Qs + 64 * QS_S;          // [d][j]  64 x KS_S
    float* Vs = Ks + 64 * KS_S;          // [j][d] 192 x VS_S
    float* Ss = Vs + 192 * VS_S;         // [j][q] 192 x SS_S
    __shared__ float s_inv[64];

    const int tid = threadIdx.x;
    const int qt  = blockIdx.x;
    const int h   = blockIdx.y;
    const int q0  = qt * 64;

    const float* __restrict__ Qg = g_Q + ((size_t)h * L + q0) * HD;
    const float* __restrict__ Kg = g_K + (size_t)h * L * HD;
    const float* __restrict__ Vg = g_V + (size_t)h * L * HD;

    // ---- load tiles (coalesced global, transposed smem for Q/K) ----
    for (int idx = tid; idx < 64 * 64; idx += 256) {
        const int d = idx & 63, q = idx >> 6;
        Qs[d * QS_S + q] = Qg[q * HD + d];
    }
    for (int idx = tid; idx < 192 * 64; idx += 256) {
        const int d = idx & 63, j = idx >> 6;
        int jg = q0 - 64 + j;
        jg = max(0, min(L - 1, jg));     // clamp; masked later
        Ks[d * KS_S + j] = Kg[(size_t)jg * HD + d];
        Vs[j * VS_S + d] = Vg[(size_t)jg * HD + d];
    }
    __syncthreads();

    // ---- scores: Ss[j][q] = sum_d Qs[d][q] * Ks[d][j]  (12x4 microtile) ----
    {
        const int jj = tid >> 4;          // 0..15 -> j base = jj*12
        const int qq = tid & 15;          // 0..15 -> q base = qq*4
        float acc[12][4] = {};
#pragma unroll 8
        for (int d = 0; d < 64; ++d) {
            const float4 qv4 = *(const float4*)&Qs[d * QS_S + qq * 4];
            const float qv[4] = {qv4.x, qv4.y, qv4.z, qv4.w};
            const float4 k0 = *(const float4*)&Ks[d * KS_S + jj * 12 + 0];
            const float4 k1 = *(const float4*)&Ks[d * KS_S + jj * 12 + 4];
            const float4 k2 = *(const float4*)&Ks[d * KS_S + jj * 12 + 8];
            const float kv[12] = {k0.x, k0.y, k0.z, k0.w,
                                  k1.x, k1.y, k1.z, k1.w,
                                  k2.x, k2.y, k2.z, k2.w};
#pragma unroll
            for (int a = 0; a < 12; ++a)
#pragma unroll
                for (int b = 0; b < 4; ++b)
                    acc[a][b] = fmaf(kv[a], qv[b], acc[a][b]);
        }
#pragma unroll
        for (int a = 0; a < 12; ++a) {
            float4 st = {acc[a][0], acc[a][1], acc[a][2], acc[a][3]};
            *(float4*)&Ss[(jj * 12 + a) * SS_S + qq * 4] = st;
        }
    }
    __syncthreads();

    // ---- masked softmax over j for each q (4 threads per query) ----
    {
        const int q   = tid >> 2;
        const int sub = tid & 3;
        // valid local-j range: j in [max(q, 64-q0), min(q+128, 4159-q0)]
        const int jlo = max(q, 64 - q0);
        const int jhi = min(q + 128, (L - 1) - (q0 - 64));
        float mx = -1e30f;
        for (int j = jlo + sub; j <= jhi; j += 4)
            mx = fmaxf(mx, Ss[j * SS_S + q]);
        mx = fmaxf(mx, __shfl_xor_sync(0xffffffffu, mx, 1));
        mx = fmaxf(mx, __shfl_xor_sync(0xffffffffu, mx, 2));
        float sum = 0.f;
        for (int j = sub; j < 192; j += 4) {
            float p = 0.f;
            if (j >= jlo && j <= jhi) {
                p = __expf((Ss[j * SS_S + q] - mx) * ATTN_SCALE);
                sum += p;
            }
            Ss[j * SS_S + q] = p;
        }
        sum += __shfl_xor_sync(0xffffffffu, sum, 1);
        sum += __shfl_xor_sync(0xffffffffu, sum, 2);
        if (sub == 0) s_inv[q] = 1.f / sum;
    }
    __syncthreads();

    // ---- O[q][d] = (sum_j Ss[j][q] * Vs[j][d]) * inv_sum[q] ----
    {
        const int ty = tid >> 4;          // q base = ty*4
        const int tx = tid & 15;          // d base = tx*4
        float acc[4][4] = {};
#pragma unroll 4
        for (int j = 0; j < 192; ++j) {
            const float4 p4 = *(const float4*)&Ss[j * SS_S + ty * 4];
            const float4 v4 = *(const float4*)&Vs[j * VS_S + tx * 4];
            const float p_[4] = {p4.x, p4.y, p4.z, p4.w};
            const float v_[4] = {v4.x, v4.y, v4.z, v4.w};
#pragma unroll
            for (int m = 0; m < 4; ++m)
#pragma unroll
                for (int n = 0; n < 4; ++n)
                    acc[m][n] = fmaf(p_[m], v_[n], acc[m][n]);
        }
#pragma unroll
        for (int m = 0; m < 4; ++m) {
            const int q = ty * 4 + m;
            const float inv = s_inv[q];
            float4 st = {acc[m][0] * inv, acc[m][1] * inv,
                         acc[m][2] * inv, acc[m][3] * inv};
            *(float4*)&g_attn[(size_t)(q0 + q) * DM + h * HD + tx * 4] = st;
        }
    }
}

// ---------------- launch ----------------
extern "C" void kernel_launch(void* const* d_in, const int* in_sizes, int n_in,
                              void* d_out, int out_size)
{
    const float* q  = (const float*)d_in[0];
    const float* k  = (const float*)d_in[1];
    const float* v  = (const float*)d_in[2];
    const float* Wq = (const float*)d_in[3];
    const float* bq = (const float*)d_in[4];
    const float* Wk = (const float*)d_in[5];
    const float* bk = (const float*)d_in[6];
    const float* Wv = (const float*)d_in[7];
    const float* bv = (const float*)d_in[8];
    const float* Wo = (const float*)d_in[9];
    const float* bo = (const float*)d_in[10];
    float* out = (float*)d_out;

    cudaFuncSetAttribute(attn_kernel,
                         cudaFuncAttributeMaxDynamicSharedMemorySize,
                         ATT_SMEM_BYTES);

    qkv_proj_kernel<<<dim3(L / 64, NH, 3), 256>>>(q, k, v, Wq, Wk, Wv, bq, bk, bv);
    attn_kernel<<<dim3(L / 64, NH), 256, ATT_SMEM_BYTES>>>();
    out_proj_kernel<<<dim3(L / 64, DM / 64), 256>>>(Wo, bo, out);
}

// round 2
// speedup vs baseline: 1.3171x; 1.3171x over previous
#include <cuda_runtime.h>

#define L    4096
#define DM   768
#define NH   12
#define HD   64
#define ATTN_SCALE 0.125f   // 1/sqrt(64)

// ---------------- scratch (no allocations allowed) ----------------
__device__ float g_Q[L * DM];        // row-major [i][h*64+d]
__device__ float g_K[L * DM];
__device__ float g_V[L * DM];
__device__ float g_attn[L * DM];     // [i][h*64+d]

// ---------------- SGEMM: C[i,j] = sum_k X[i,k]*W[j,k] + b[j] ----------------
// BM=BN=128, BK=16, 256 threads, 8x8 microtile. N=K=768 fixed, M=4096.

#define BM 128
#define BN 128
#define BK 16
#define APAD 4

__device__ __forceinline__ void gemm_body(const float* __restrict__ X,
                                          const float* __restrict__ W,
                                          const float* __restrict__ Bb,
                                          float* __restrict__ C,
                                          int i0, int j0)
{
    __shared__ float As[BK][BM + APAD];
    __shared__ float Bs[BK][BN + APAD];

    const int tid = threadIdx.x;
    const int tx  = tid & 15;         // col group 0..15
    const int ty  = tid >> 4;         // row group 0..15
    const int lr  = tid >> 2;         // 0..63
    const int lk  = (tid & 3) * 4;    // 0,4,8,12

    float acc[8][8] = {};
    float ar[8], br[8];

    for (int kt = 0; kt < DM; kt += BK) {
#pragma unroll
        for (int half = 0; half < 2; ++half) {
            const int r = lr + half * 64;
            const float4 a4 = *(const float4*)&X[(size_t)(i0 + r) * DM + kt + lk];
            As[lk + 0][r] = a4.x; As[lk + 1][r] = a4.y;
            As[lk + 2][r] = a4.z; As[lk + 3][r] = a4.w;
            const float4 b4 = *(const float4*)&W[(size_t)(j0 + r) * DM + kt + lk];
            Bs[lk + 0][r] = b4.x; Bs[lk + 1][r] = b4.y;
            Bs[lk + 2][r] = b4.z; Bs[lk + 3][r] = b4.w;
        }
        __syncthreads();

#pragma unroll
        for (int k = 0; k < BK; ++k) {
            *(float4*)&ar[0] = *(const float4*)&As[k][ty * 4];
            *(float4*)&ar[4] = *(const float4*)&As[k][64 + ty * 4];
            *(float4*)&br[0] = *(const float4*)&Bs[k][tx * 4];
            *(float4*)&br[4] = *(const float4*)&Bs[k][64 + tx * 4];
#pragma unroll
            for (int m = 0; m < 8; ++m)
#pragma unroll
                for (int n = 0; n < 8; ++n)
                    acc[m][n] = fmaf(ar[m], br[n], acc[m][n]);
        }
        __syncthreads();
    }

    // epilogue with bias
    float bb[8];
    *(float4*)&bb[0] = *(const float4*)&Bb[j0 + tx * 4];
    *(float4*)&bb[4] = *(const float4*)&Bb[j0 + 64 + tx * 4];

#pragma unroll
    for (int mh = 0; mh < 2; ++mh) {
#pragma unroll
        for (int m = 0; m < 4; ++m) {
            const int i = i0 + mh * 64 + ty * 4 + m;
            const int mi = mh * 4 + m;
            float4 s0 = {acc[mi][0] + bb[0], acc[mi][1] + bb[1],
                         acc[mi][2] + bb[2], acc[mi][3] + bb[3]};
            float4 s1 = {acc[mi][4] + bb[4], acc[mi][5] + bb[5],
                         acc[mi][6] + bb[6], acc[mi][7] + bb[7]};
            *(float4*)&C[(size_t)i * DM + j0 + tx * 4] = s0;
            *(float4*)&C[(size_t)i * DM + j0 + 64 + tx * 4] = s1;
        }
    }
}

__global__ void __launch_bounds__(256)
qkv_proj_kernel(const float* __restrict__ xq, const float* __restrict__ xk, const float* __restrict__ xv,
                const float* __restrict__ wq, const float* __restrict__ wk, const float* __restrict__ wv,
                const float* __restrict__ bq, const float* __restrict__ bk, const float* __restrict__ bv)
{
    const int z = blockIdx.z;
    const float* X  = (z == 0) ? xq : (z == 1) ? xk : xv;
    const float* W  = (z == 0) ? wq : (z == 1) ? wk : wv;
    const float* Bb = (z == 0) ? bq : (z == 1) ? bk : bv;
    float* dst      = (z == 0) ? g_Q : (z == 1) ? g_K : g_V;
    gemm_body(X, W, Bb, dst, blockIdx.x * BM, blockIdx.y * BN);
}

__global__ void __launch_bounds__(256)
out_proj_kernel(const float* __restrict__ W, const float* __restrict__ Bb,
                float* __restrict__ out)
{
    gemm_body(g_attn, W, Bb, out, blockIdx.x * BM, blockIdx.y * BN);
}

// ---------------- sliding-window attention ----------------
// One block per (64-query tile, head). Keys needed: [q0-64, q0+127] -> 192 rows.
#define QS_S 68
#define KS_S 196
#define VS_S 68
#define SS_S 68
#define ATT_SMEM_FLOATS (64 * QS_S + 64 * KS_S + 192 * VS_S + 192 * SS_S)
#define ATT_SMEM_BYTES  (ATT_SMEM_FLOATS * 4)

__global__ void __launch_bounds__(256)
attn_kernel()
{
    extern __shared__ float sm[];
    float* Qs = sm;                      // [d][q]  64 x QS_S
    float* Ks = Qs + 64 * QS_S;          // [d][j]  64 x KS_S
    float* Vs = Ks + 64 * KS_S;          // [j][d] 192 x VS_S
    float* Ss = Vs + 192 * VS_S;         // [j][q] 192 x SS_S
    __shared__ float s_inv[64];

    const int tid = threadIdx.x;
    const int qt  = blockIdx.x;
    const int h   = blockIdx.y;
    const int q0  = qt * 64;
    const int c0  = h * HD;              // column base in row-major [L][DM]

    // ---- load tiles (coalesced global, transposed smem for Q/K) ----
    for (int idx = tid; idx < 64 * 64; idx += 256) {
        const int d = idx & 63, q = idx >> 6;
        Qs[d * QS_S + q] = g_Q[(size_t)(q0 + q) * DM + c0 + d];
    }
    for (int idx = tid; idx < 192 * 64; idx += 256) {
        const int d = idx & 63, j = idx >> 6;
        int jg = q0 - 64 + j;
        jg = max(0, min(L - 1, jg));     // clamp; masked later
        Ks[d * KS_S + j] = g_K[(size_t)jg * DM + c0 + d];
        Vs[j * VS_S + d] = g_V[(size_t)jg * DM + c0 + d];
    }
    __syncthreads();

    // ---- scores: Ss[j][q] = sum_d Qs[d][q] * Ks[d][j]  (12x4 microtile) ----
    {
        const int jj = tid >> 4;          // j base = jj*12
        const int qq = tid & 15;          // q base = qq*4
        float acc[12][4] = {};
#pragma unroll 8
        for (int d = 0; d < 64; ++d) {
            const float4 qv4 = *(const float4*)&Qs[d * QS_S + qq * 4];
            const float qv[4] = {qv4.x, qv4.y, qv4.z, qv4.w};
            const float4 k0 = *(const float4*)&Ks[d * KS_S + jj * 12 + 0];
            const float4 k1 = *(const float4*)&Ks[d * KS_S + jj * 12 + 4];
            const float4 k2 = *(const float4*)&Ks[d * KS_S + jj * 12 + 8];
            const float kv[12] = {k0.x, k0.y, k0.z, k0.w,
                                  k1.x, k1.y, k1.z, k1.w,
                                  k2.x, k2.y, k2.z, k2.w};
#pragma unroll
            for (int a = 0; a < 12; ++a)
#pragma unroll
                for (int b = 0; b < 4; ++b)
                    acc[a][b] = fmaf(kv[a], qv[b], acc[a][b]);
        }
#pragma unroll
        for (int a = 0; a < 12; ++a) {
            float4 st = {acc[a][0], acc[a][1], acc[a][2], acc[a][3]};
            *(float4*)&Ss[(jj * 12 + a) * SS_S + qq * 4] = st;
        }
    }
    __syncthreads();

    // ---- masked softmax over j for each q (4 threads per query) ----
    {
        const int q   = tid >> 2;
        const int sub = tid & 3;
        const int jlo = max(q, 64 - q0);
        const int jhi = min(q + 128, (L - 1) - (q0 - 64));
        float mx = -1e30f;
        for (int j = jlo + sub; j <= jhi; j += 4)
            mx = fmaxf(mx, Ss[j * SS_S + q]);
        mx = fmaxf(mx, __shfl_xor_sync(0xffffffffu, mx, 1));
        mx = fmaxf(mx, __shfl_xor_sync(0xffffffffu, mx, 2));
        float sum = 0.f;
        for (int j = sub; j < 192; j += 4) {
            float p = 0.f;
            if (j >= jlo && j <= jhi) {
                p = __expf((Ss[j * SS_S + q] - mx) * ATTN_SCALE);
                sum += p;
            }
            Ss[j * SS_S + q] = p;
        }
        sum += __shfl_xor_sync(0xffffffffu, sum, 1);
        sum += __shfl_xor_sync(0xffffffffu, sum, 2);
        if (sub == 0) s_inv[q] = 1.f / sum;
    }
    __syncthreads();

    // ---- O[q][d] = (sum_j Ss[j][q] * Vs[j][d]) * inv_sum[q] ----
    {
        const int ty = tid >> 4;          // q base = ty*4
        const int tx = tid & 15;          // d base = tx*4
        float acc[4][4] = {};
#pragma unroll 4
        for (int j = 0; j < 192; ++j) {
            const float4 p4 = *(const float4*)&Ss[j * SS_S + ty * 4];
            const float4 v4 = *(const float4*)&Vs[j * VS_S + tx * 4];
            const float p_[4] = {p4.x, p4.y, p4.z, p4.w};
            const float v_[4] = {v4.x, v4.y, v4.z, v4.w};
#pragma unroll
            for (int m = 0; m < 4; ++m)
#pragma unroll
                for (int n = 0; n < 4; ++n)
                    acc[m][n] = fmaf(p_[m], v_[n], acc[m][n]);
        }
#pragma unroll
        for (int m = 0; m < 4; ++m) {
            const int q = ty * 4 + m;
            const float inv = s_inv[q];
            float4 st = {acc[m][0] * inv, acc[m][1] * inv,
                         acc[m][2] * inv, acc[m][3] * inv};
            *(float4*)&g_attn[(size_t)(q0 + q) * DM + c0 + tx * 4] = st;
        }
    }
}

// ---------------- launch ----------------
extern "C" void kernel_launch(void* const* d_in, const int* in_sizes, int n_in,
                              void* d_out, int out_size)
{
    const float* q  = (const float*)d_in[0];
    const float* k  = (const float*)d_in[1];
    const float* v  = (const float*)d_in[2];
    const float* Wq = (const float*)d_in[3];
    const float* bq = (const float*)d_in[4];
    const float* Wk = (const float*)d_in[5];
    const float* bk = (const float*)d_in[6];
    const float* Wv = (const float*)d_in[7];
    const float* bv = (const float*)d_in[8];
    const float* Wo = (const float*)d_in[9];
    const float* bo = (const float*)d_in[10];
    float* out = (float*)d_out;

    cudaFuncSetAttribute(attn_kernel,
                         cudaFuncAttributeMaxDynamicSharedMemorySize,
                         ATT_SMEM_BYTES);

    qkv_proj_kernel<<<dim3(L / BM, DM / BN, 3), 256>>>(q, k, v, Wq, Wk, Wv, bq, bk, bv);
    attn_kernel<<<dim3(L / 64, NH), 256, ATT_SMEM_BYTES>>>();
    out_proj_kernel<<<dim3(L / BM, DM / BN), 256>>>(Wo, bo, out);
}

// round 4
// speedup vs baseline: 2.4193x; 1.8369x over previous
#include <cuda_runtime.h>
#include <cstdint>

#define L    4096
#define DM   768
#define NH   12
#define HD   64
#define ATTN_SCALE 0.125f   // 1/sqrt(64)

// ---------------- scratch (no allocations allowed) ----------------
__device__ float g_Q[L * DM];        // row-major [i][h*64+d]
__device__ float g_K[L * DM];
__device__ float g_V[L * DM];
__device__ float g_attn[L * DM];     // [i][h*64+d]

// =======================================================================
// helpers
// =======================================================================
__device__ __forceinline__ uint32_t f2tf32(float f) {
    uint32_t u;
    asm("cvt.rna.tf32.f32 %0, %1;" : "=r"(u) : "f"(f));
    return u;
}

__device__ __forceinline__ void mma_tf32(float c[4], const uint32_t a[4], const uint32_t b[2]) {
    asm volatile(
        "mma.sync.aligned.m16n8k8.row.col.f32.tf32.tf32.f32 "
        "{%0,%1,%2,%3}, {%4,%5,%6,%7}, {%8,%9}, {%0,%1,%2,%3};"
        : "+f"(c[0]), "+f"(c[1]), "+f"(c[2]), "+f"(c[3])
        : "r"(a[0]), "r"(a[1]), "r"(a[2]), "r"(a[3]), "r"(b[0]), "r"(b[1]));
}

// =======================================================================
// tf32 tensor-core GEMM: C[i,j] = sum_k X[i,k]*W[j,k] + b[j]
// CTA 128x128, BK=32, 256 threads (8 warps, 4x2), warp tile 32x64.
// smem: As/Bs double-buffered, padded row stride 36 floats.
// =======================================================================
#define BMM 128
#define BKT 32
#define SST 36                               // padded row stride (floats)
#define BUF_FLOATS (BMM * SST)               // 4608
#define GEMM_SMEM (4 * BUF_FLOATS * 4)       // A0,B0,A1,B1 = 73728 bytes

__device__ __forceinline__ void g2r(const float* __restrict__ src, int row0, int kt,
                                    int tid, float4 r[4]) {
#pragma unroll
    for (int i = 0; i < 4; ++i) {
        const int f = tid + i * 256;         // 0..1023
        const int r_ = f >> 3;               // 0..127
        const int c_ = f & 7;                // 0..7
        r[i] = *(const float4*)&src[(size_t)(row0 + r_) * DM + kt * BKT + c_ * 4];
    }
}
__device__ __forceinline__ void r2s(float* __restrict__ dst, int tid, const float4 r[4]) {
#pragma unroll
    for (int i = 0; i < 4; ++i) {
        const int f = tid + i * 256;
        const int r_ = f >> 3;
        const int c_ = f & 7;
        uint4 u;
        u.x = f2tf32(r[i].x); u.y = f2tf32(r[i].y);
        u.z = f2tf32(r[i].z); u.w = f2tf32(r[i].w);
        *(uint4*)&dst[r_ * SST + c_ * 4] = u;
    }
}

__device__ __forceinline__ void gemm_mma_body(const float* __restrict__ X,
                                              const float* __restrict__ W,
                                              const float* __restrict__ Bb,
                                              float* __restrict__ C,
                                              int i0, int j0)
{
    extern __shared__ float smf[];
    float* As = smf;                          // [2][BUF_FLOATS]
    float* Bs = smf + 2 * BUF_FLOATS;

    const int tid  = threadIdx.x;
    const int wid  = tid >> 5;
    const int lane = tid & 31;
    const int gq   = lane >> 2;               // groupID 0..7
    const int tg   = lane & 3;                // threadID_in_group 0..3
    const int wm0  = (wid & 3) * 32;          // warp M base
    const int wn0  = (wid >> 2) * 64;         // warp N base

    float acc[2][8][4] = {};                  // [m-subtile][n-subtile][frag]
    float4 areg[4], breg[4];

    // prologue: chunk 0
    g2r(X, i0, 0, tid, areg);
    g2r(W, j0, 0, tid, breg);
    r2s(As, tid, areg);
    r2s(Bs, tid, breg);
    __syncthreads();

#define NCHUNK (DM / BKT)                     // 24
    for (int kt = 0; kt < NCHUNK; ++kt) {
        const int cur = kt & 1;
        const int nxt = cur ^ 1;
        const bool more = (kt + 1 < NCHUNK);
        if (more) {
            g2r(X, i0, kt + 1, tid, areg);
            g2r(W, j0, kt + 1, tid, breg);
        }
        const float* Ac = As + cur * BUF_FLOATS;
        const float* Bc = Bs + cur * BUF_FLOATS;

#pragma unroll
        for (int kk = 0; kk < BKT; kk += 8) {
            uint32_t af[2][4], bf[8][2];
#pragma unroll
            for (int mt = 0; mt < 2; ++mt) {
                const int r = wm0 + mt * 16 + gq;
                af[mt][0] = __float_as_uint(Ac[(r    ) * SST + kk + tg    ]);
                af[mt][1] = __float_as_uint(Ac[(r + 8) * SST + kk + tg    ]);
                af[mt][2] = __float_as_uint(Ac[(r    ) * SST + kk + tg + 4]);
                af[mt][3] = __float_as_uint(Ac[(r + 8) * SST + kk + tg + 4]);
            }
#pragma unroll
            for (int nt = 0; nt < 8; ++nt) {
                const int n = wn0 + nt * 8 + gq;
                bf[nt][0] = __float_as_uint(Bc[n * SST + kk + tg    ]);
                bf[nt][1] = __float_as_uint(Bc[n * SST + kk + tg + 4]);
            }
#pragma unroll
            for (int mt = 0; mt < 2; ++mt)
#pragma unroll
                for (int nt = 0; nt < 8; ++nt)
                    mma_tf32(acc[mt][nt], af[mt], bf[nt]);
        }

        if (more) {
            r2s(As + nxt * BUF_FLOATS, tid, areg);
            r2s(Bs + nxt * BUF_FLOATS, tid, breg);
        }
        __syncthreads();
    }

    // epilogue: add bias, store float2 pairs
#pragma unroll
    for (int nt = 0; nt < 8; ++nt) {
        const int col = j0 + wn0 + nt * 8 + 2 * tg;
        const float2 bb = *(const float2*)&Bb[col];
#pragma unroll
        for (int mt = 0; mt < 2; ++mt) {
            const int r = i0 + wm0 + mt * 16 + gq;
            float2 s0 = {acc[mt][nt][0] + bb.x, acc[mt][nt][1] + bb.y};
            float2 s1 = {acc[mt][nt][2] + bb.x, acc[mt][nt][3] + bb.y};
            *(float2*)&C[(size_t)r * DM + col] = s0;
            *(float2*)&C[(size_t)(r + 8) * DM + col] = s1;
        }
    }
}

__global__ void __launch_bounds__(256)
qkv_proj_kernel(const float* __restrict__ xq, const float* __restrict__ xk, const float* __restrict__ xv,
                const float* __restrict__ wq, const float* __restrict__ wk, const float* __restrict__ wv,
                const float* __restrict__ bq, const float* __restrict__ bk, const float* __restrict__ bv)
{
    const int z = blockIdx.z;
    const float* X  = (z == 0) ? xq : (z == 1) ? xk : xv;
    const float* W  = (z == 0) ? wq : (z == 1) ? wk : wv;
    const float* Bb = (z == 0) ? bq : (z == 1) ? bk : bv;
    float* dst      = (z == 0) ? g_Q : (z == 1) ? g_K : g_V;
    gemm_mma_body(X, W, Bb, dst, blockIdx.x * BMM, blockIdx.y * BMM);
}

__global__ void __launch_bounds__(256)
out_proj_kernel(const float* __restrict__ W, const float* __restrict__ Bb,
                float* __restrict__ out)
{
    gemm_mma_body(g_attn, W, Bb, out, blockIdx.x * BMM, blockIdx.y * BMM);
}

// =======================================================================
// sliding-window attention (fp32 FFMA, unchanged from R2)
// =======================================================================
#define QS_S 68
#define KS_S 196
#define VS_S 68
#define SS_S 68
#define ATT_SMEM_FLOATS (64 * QS_S + 64 * KS_S + 192 * VS_S + 192 * SS_S)
#define ATT_SMEM_BYTES  (ATT_SMEM_FLOATS * 4)

__global__ void __launch_bounds__(256)
attn_kernel()
{
    extern __shared__ float sm[];
    float* Qs = sm;                      // [d][q]  64 x QS_S
    float* Ks = Qs + 64 * QS_S;          // [d][j]  64 x KS_S
    float* Vs = Ks + 64 * KS_S;          // [j][d] 192 x VS_S
    float* Ss = Vs + 192 * VS_S;         // [j][q] 192 x SS_S
    __shared__ float s_inv[64];

    const int tid = threadIdx.x;
    const int q0  = blockIdx.x * 64;
    const int h   = blockIdx.y;
    const int c0  = h * HD;

    for (int idx = tid; idx < 64 * 64; idx += 256) {
        const int d = idx & 63, q = idx >> 6;
        Qs[d * QS_S + q] = g_Q[(size_t)(q0 + q) * DM + c0 + d];
    }
    for (int idx = tid; idx < 192 * 64; idx += 256) {
        const int d = idx & 63, j = idx >> 6;
        int jg = q0 - 64 + j;
        jg = max(0, min(L - 1, jg));
        Ks[d * KS_S + j] = g_K[(size_t)jg * DM + c0 + d];
        Vs[j * VS_S + d] = g_V[(size_t)jg * DM + c0 + d];
    }
    __syncthreads();

    {   // scores: Ss[j][q] = sum_d Qs[d][q]*Ks[d][j]
        const int jj = tid >> 4;
        const int qq = tid & 15;
        float acc[12][4] = {};
#pragma unroll 8
        for (int d = 0; d < 64; ++d) {
            const float4 qv4 = *(const float4*)&Qs[d * QS_S + qq * 4];
            const float qv[4] = {qv4.x, qv4.y, qv4.z, qv4.w};
            const float4 k0 = *(const float4*)&Ks[d * KS_S + jj * 12 + 0];
            const float4 k1 = *(const float4*)&Ks[d * KS_S + jj * 12 + 4];
            const float4 k2 = *(const float4*)&Ks[d * KS_S + jj * 12 + 8];
            const float kv[12] = {k0.x, k0.y, k0.z, k0.w,
                                  k1.x, k1.y, k1.z, k1.w,
                                  k2.x, k2.y, k2.z, k2.w};
#pragma unroll
            for (int a = 0; a < 12; ++a)
#pragma unroll
                for (int b = 0; b < 4; ++b)
                    acc[a][b] = fmaf(kv[a], qv[b], acc[a][b]);
        }
#pragma unroll
        for (int a = 0; a < 12; ++a) {
            float4 st = {acc[a][0], acc[a][1], acc[a][2], acc[a][3]};
            *(float4*)&Ss[(jj * 12 + a) * SS_S + qq * 4] = st;
        }
    }
    __syncthreads();

    {   // masked softmax
        const int q   = tid >> 2;
        const int sub = tid & 3;
        const int jlo = max(q, 64 - q0);
        const int jhi = min(q + 128, (L - 1) - (q0 - 64));
        float mx = -1e30f;
        for (int j = jlo + sub; j <= jhi; j += 4)
            mx = fmaxf(mx, Ss[j * SS_S + q]);
        mx = fmaxf(mx, __shfl_xor_sync(0xffffffffu, mx, 1));
        mx = fmaxf(mx, __shfl_xor_sync(0xffffffffu, mx, 2));
        float sum = 0.f;
        for (int j = sub; j < 192; j += 4) {
            float p = 0.f;
            if (j >= jlo && j <= jhi) {
                p = __expf((Ss[j * SS_S + q] - mx) * ATTN_SCALE);
                sum += p;
            }
            Ss[j * SS_S + q] = p;
        }
        sum += __shfl_xor_sync(0xffffffffu, sum, 1);
        sum += __shfl_xor_sync(0xffffffffu, sum, 2);
        if (sub == 0) s_inv[q] = 1.f / sum;
    }
    __syncthreads();

    {   // O = P·V
        const int ty = tid >> 4;
        const int tx = tid & 15;
        float acc[4][4] = {};
#pragma unroll 4
        for (int j = 0; j < 192; ++j) {
            const float4 p4 = *(const float4*)&Ss[j * SS_S + ty * 4];
            const float4 v4 = *(const float4*)&Vs[j * VS_S + tx * 4];
            const float p_[4] = {p4.x, p4.y, p4.z, p4.w};
            const float v_[4] = {v4.x, v4.y, v4.z, v4.w};
#pragma unroll
            for (int m = 0; m < 4; ++m)
#pragma unroll
                for (int n = 0; n < 4; ++n)
                    acc[m][n] = fmaf(p_[m], v_[n], acc[m][n]);
        }
#pragma unroll
        for (int m = 0; m < 4; ++m) {
            const int q = ty * 4 + m;
            const float inv = s_inv[q];
            float4 st = {acc[m][0] * inv, acc[m][1] * inv,
                         acc[m][2] * inv, acc[m][3] * inv};
            *(float4*)&g_attn[(size_t)(q0 + q) * DM + c0 + tx * 4] = st;
        }
    }
}

// ---------------- launch ----------------
extern "C" void kernel_launch(void* const* d_in, const int* in_sizes, int n_in,
                              void* d_out, int out_size)
{
    const float* q  = (const float*)d_in[0];
    const float* k  = (const float*)d_in[1];
    const float* v  = (const float*)d_in[2];
    const float* Wq = (const float*)d_in[3];
    const float* bq = (const float*)d_in[4];
    const float* Wk = (const float*)d_in[5];
    const float* bk = (const float*)d_in[6];
    const float* Wv = (const float*)d_in[7];
    const float* bv = (const float*)d_in[8];
    const float* Wo = (const float*)d_in[9];
    const float* bo = (const float*)d_in[10];
    float* out = (float*)d_out;

    cudaFuncSetAttribute(qkv_proj_kernel,
                         cudaFuncAttributeMaxDynamicSharedMemorySize, GEMM_SMEM);
    cudaFuncSetAttribute(out_proj_kernel,
                         cudaFuncAttributeMaxDynamicSharedMemorySize, GEMM_SMEM);
    cudaFuncSetAttribute(attn_kernel,
                         cudaFuncAttributeMaxDynamicSharedMemorySize, ATT_SMEM_BYTES);

    qkv_proj_kernel<<<dim3(L / BMM, DM / BMM, 3), 256, GEMM_SMEM>>>(q, k, v, Wq, Wk, Wv, bq, bk, bv);
    attn_kernel<<<dim3(L / 64, NH), 256, ATT_SMEM_BYTES>>>();
    out_proj_kernel<<<dim3(L / BMM, DM / BMM), 256, GEMM_SMEM>>>(Wo, bo, out);
}

// round 5
// speedup vs baseline: 2.8119x; 1.1622x over previous
#include <cuda_runtime.h>
#include <cstdint>

#define L    4096
#define DM   768
#define NH   12
#define HD   64
#define ATTN_SCALE 0.125f   // 1/sqrt(64)

// ---------------- scratch (no allocations allowed) ----------------
__device__ float g_Q[L * DM];        // row-major [i][h*64+d]
__device__ float g_K[L * DM];
__device__ float g_V[L * DM];
__device__ float g_attn[L * DM];     // [i][h*64+d]

// =======================================================================
// helpers
// =======================================================================
__device__ __forceinline__ uint32_t f2tf32(float f) {
    uint32_t u;
    asm("cvt.rna.tf32.f32 %0, %1;" : "=r"(u) : "f"(f));
    return u;
}

__device__ __forceinline__ void mma_tf32(float c[4], const uint32_t a[4], const uint32_t b[2]) {
    asm volatile(
        "mma.sync.aligned.m16n8k8.row.col.f32.tf32.tf32.f32 "
        "{%0,%1,%2,%3}, {%4,%5,%6,%7}, {%8,%9}, {%0,%1,%2,%3};"
        : "+f"(c[0]), "+f"(c[1]), "+f"(c[2]), "+f"(c[3])
        : "r"(a[0]), "r"(a[1]), "r"(a[2]), "r"(a[3]), "r"(b[0]), "r"(b[1]));
}

// =======================================================================
// tf32 tensor-core GEMM: C[i,j] = sum_k X[i,k]*W[j,k] + b[j]   (as R4)
// =======================================================================
#define BMM 128
#define BKT 32
#define SST 36
#define BUF_FLOATS (BMM * SST)
#define GEMM_SMEM (4 * BUF_FLOATS * 4)

__device__ __forceinline__ void g2r(const float* __restrict__ src, int row0, int kt,
                                    int tid, float4 r[4]) {
#pragma unroll
    for (int i = 0; i < 4; ++i) {
        const int f = tid + i * 256;
        const int r_ = f >> 3;
        const int c_ = f & 7;
        r[i] = *(const float4*)&src[(size_t)(row0 + r_) * DM + kt * BKT + c_ * 4];
    }
}
__device__ __forceinline__ void r2s(float* __restrict__ dst, int tid, const float4 r[4]) {
#pragma unroll
    for (int i = 0; i < 4; ++i) {
        const int f = tid + i * 256;
        const int r_ = f >> 3;
        const int c_ = f & 7;
        uint4 u;
        u.x = f2tf32(r[i].x); u.y = f2tf32(r[i].y);
        u.z = f2tf32(r[i].z); u.w = f2tf32(r[i].w);
        *(uint4*)&dst[r_ * SST + c_ * 4] = u;
    }
}

__device__ __forceinline__ void gemm_mma_body(const float* __restrict__ X,
                                              const float* __restrict__ W,
                                              const float* __restrict__ Bb,
                                              float* __restrict__ C,
                                              int i0, int j0)
{
    extern __shared__ float smf[];
    float* As = smf;
    float* Bs = smf + 2 * BUF_FLOATS;

    const int tid  = threadIdx.x;
    const int wid  = tid >> 5;
    const int lane = tid & 31;
    const int gq   = lane >> 2;
    const int tg   = lane & 3;
    const int wm0  = (wid & 3) * 32;
    const int wn0  = (wid >> 2) * 64;

    float acc[2][8][4] = {};
    float4 areg[4], breg[4];

    g2r(X, i0, 0, tid, areg);
    g2r(W, j0, 0, tid, breg);
    r2s(As, tid, areg);
    r2s(Bs, tid, breg);
    __syncthreads();

#define NCHUNK (DM / BKT)
    for (int kt = 0; kt < NCHUNK; ++kt) {
        const int cur = kt & 1;
        const int nxt = cur ^ 1;
        const bool more = (kt + 1 < NCHUNK);
        if (more) {
            g2r(X, i0, kt + 1, tid, areg);
            g2r(W, j0, kt + 1, tid, breg);
        }
        const float* Ac = As + cur * BUF_FLOATS;
        const float* Bc = Bs + cur * BUF_FLOATS;

#pragma unroll
        for (int kk = 0; kk < BKT; kk += 8) {
            uint32_t af[2][4], bf[8][2];
#pragma unroll
            for (int mt = 0; mt < 2; ++mt) {
                const int r = wm0 + mt * 16 + gq;
                af[mt][0] = __float_as_uint(Ac[(r    ) * SST + kk + tg    ]);
                af[mt][1] = __float_as_uint(Ac[(r + 8) * SST + kk + tg    ]);
                af[mt][2] = __float_as_uint(Ac[(r    ) * SST + kk + tg + 4]);
                af[mt][3] = __float_as_uint(Ac[(r + 8) * SST + kk + tg + 4]);
            }
#pragma unroll
            for (int nt = 0; nt < 8; ++nt) {
                const int n = wn0 + nt * 8 + gq;
                bf[nt][0] = __float_as_uint(Bc[n * SST + kk + tg    ]);
                bf[nt][1] = __float_as_uint(Bc[n * SST + kk + tg + 4]);
            }
#pragma unroll
            for (int mt = 0; mt < 2; ++mt)
#pragma unroll
                for (int nt = 0; nt < 8; ++nt)
                    mma_tf32(acc[mt][nt], af[mt], bf[nt]);
        }

        if (more) {
            r2s(As + nxt * BUF_FLOATS, tid, areg);
            r2s(Bs + nxt * BUF_FLOATS, tid, breg);
        }
        __syncthreads();
    }

#pragma unroll
    for (int nt = 0; nt < 8; ++nt) {
        const int col = j0 + wn0 + nt * 8 + 2 * tg;
        const float2 bb = *(const float2*)&Bb[col];
#pragma unroll
        for (int mt = 0; mt < 2; ++mt) {
            const int r = i0 + wm0 + mt * 16 + gq;
            float2 s0 = {acc[mt][nt][0] + bb.x, acc[mt][nt][1] + bb.y};
            float2 s1 = {acc[mt][nt][2] + bb.x, acc[mt][nt][3] + bb.y};
            *(float2*)&C[(size_t)r * DM + col] = s0;
            *(float2*)&C[(size_t)(r + 8) * DM + col] = s1;
        }
    }
}

__global__ void __launch_bounds__(256)
qkv_proj_kernel(const float* __restrict__ xq, const float* __restrict__ xk, const float* __restrict__ xv,
                const float* __restrict__ wq, const float* __restrict__ wk, const float* __restrict__ wv,
                const float* __restrict__ bq, const float* __restrict__ bk, const float* __restrict__ bv)
{
    const int z = blockIdx.z;
    const float* X  = (z == 0) ? xq : (z == 1) ? xk : xv;
    const float* W  = (z == 0) ? wq : (z == 1) ? wk : wv;
    const float* Bb = (z == 0) ? bq : (z == 1) ? bk : bv;
    float* dst      = (z == 0) ? g_Q : (z == 1) ? g_K : g_V;
    gemm_mma_body(X, W, Bb, dst, blockIdx.x * BMM, blockIdx.y * BMM);
}

__global__ void __launch_bounds__(256)
out_proj_kernel(const float* __restrict__ W, const float* __restrict__ Bb,
                float* __restrict__ out)
{
    gemm_mma_body(g_attn, W, Bb, out, blockIdx.x * BMM, blockIdx.y * BMM);
}

// =======================================================================
// sliding-window attention with tf32 MMA
// One block per (64-query tile, head). Keys [q0-64, q0+127] -> 192 rows.
// smem strides: Qs/Ks stride 68 (68 % 32 == 4 -> conflict-free frags),
//               Vt/Ss stride 196 (196 % 32 == 4).
// =======================================================================
#define QKS 68
#define VSS 196
#define ATT_FLOATS (64 * QKS + 192 * QKS + 64 * VSS + 64 * VSS)
#define ATT_SMEM_BYTES (ATT_FLOATS * 4)

__global__ void __launch_bounds__(256)
attn_kernel()
{
    extern __shared__ float sm[];
    float* Qs = sm;                  // [q][d]  tf32 bits, 64 x QKS
    float* Ks = Qs + 64 * QKS;       // [j][d]  192 x QKS
    float* Vt = Ks + 192 * QKS;      // [d][j]  64 x VSS
    float* Ss = Vt + 64 * VSS;       // [q][j]  64 x VSS
    __shared__ float s_inv[64];

    const int tid  = threadIdx.x;
    const int q0   = blockIdx.x * 64;
    const int h    = blockIdx.y;
    const int c0   = h * HD;
    const int wid  = tid >> 5;
    const int lane = tid & 31;
    const int gq   = lane >> 2;
    const int tg   = lane & 3;

    // ---- stage Q (row-major, coalesced float4 + cvt) ----
    for (int idx = tid; idx < 64 * 16; idx += 256) {
        const int q = idx >> 4, c4 = idx & 15;
        const float4 v = *(const float4*)&g_Q[(size_t)(q0 + q) * DM + c0 + c4 * 4];
        uint4 u = {f2tf32(v.x), f2tf32(v.y), f2tf32(v.z), f2tf32(v.w)};
        *(uint4*)&Qs[q * QKS + c4 * 4] = u;
    }
    // ---- stage K rows (clamped; masked in softmax) ----
    for (int idx = tid; idx < 192 * 16; idx += 256) {
        const int j = idx >> 4, c4 = idx & 15;
        const int jg = min(max(q0 - 64 + j, 0), L - 1);
        const float4 v = *(const float4*)&g_K[(size_t)jg * DM + c0 + c4 * 4];
        uint4 u = {f2tf32(v.x), f2tf32(v.y), f2tf32(v.z), f2tf32(v.w)};
        *(uint4*)&Ks[j * QKS + c4 * 4] = u;
    }
    // ---- stage V transposed: Vt[d][j] ----
    for (int idx = tid; idx < 192 * 64; idx += 256) {
        const int d = idx & 63, j = idx >> 6;
        const int jg = min(max(q0 - 64 + j, 0), L - 1);
        Vt[d * VSS + j] = __uint_as_float(f2tf32(g_V[(size_t)jg * DM + c0 + d]));
    }
    __syncthreads();

    // ---- phase 1: S[q][j] = sum_d Q[q][d]*K[j][d]; warp tile 16 x 96 ----
    {
        const int wm = (wid & 3) * 16;
        const int wn = (wid >> 2) * 96;
        float acc[12][4] = {};
#pragma unroll
        for (int kk = 0; kk < 64; kk += 8) {
            uint32_t a[4];
            a[0] = __float_as_uint(Qs[(wm + gq    ) * QKS + kk + tg    ]);
            a[1] = __float_as_uint(Qs[(wm + gq + 8) * QKS + kk + tg    ]);
            a[2] = __float_as_uint(Qs[(wm + gq    ) * QKS + kk + tg + 4]);
            a[3] = __float_as_uint(Qs[(wm + gq + 8) * QKS + kk + tg + 4]);
#pragma unroll
            for (int nt = 0; nt < 12; ++nt) {
                const int n = wn + nt * 8 + gq;
                uint32_t b[2];
                b[0] = __float_as_uint(Ks[n * QKS + kk + tg    ]);
                b[1] = __float_as_uint(Ks[n * QKS + kk + tg + 4]);
                mma_tf32(acc[nt], a, b);
            }
        }
#pragma unroll
        for (int nt = 0; nt < 12; ++nt) {
            const int col = wn + nt * 8 + 2 * tg;
            float2 s0 = {acc[nt][0], acc[nt][1]};
            float2 s1 = {acc[nt][2], acc[nt][3]};
            *(float2*)&Ss[(wm + gq    ) * VSS + col] = s0;
            *(float2*)&Ss[(wm + gq + 8) * VSS + col] = s1;
        }
    }
    __syncthreads();

    // ---- masked softmax over j for each q (4 threads per query) ----
    {
        const int q   = tid >> 2;
        const int sub = tid & 3;
        const int jlo = max(q, 64 - q0);
        const int jhi = min(q + 128, (L - 1) - (q0 - 64));
        float mx = -1e30f;
        for (int j = jlo + sub; j <= jhi; j += 4)
            mx = fmaxf(mx, Ss[q * VSS + j]);
        mx = fmaxf(mx, __shfl_xor_sync(0xffffffffu, mx, 1));
        mx = fmaxf(mx, __shfl_xor_sync(0xffffffffu, mx, 2));
        float sum = 0.f;
        for (int j = sub; j < 192; j += 4) {
            float p = 0.f;
            if (j >= jlo && j <= jhi)
                p = __uint_as_float(f2tf32(__expf((Ss[q * VSS + j] - mx) * ATTN_SCALE)));
            sum += p;
            Ss[q * VSS + j] = p;
        }
        sum += __shfl_xor_sync(0xffffffffu, sum, 1);
        sum += __shfl_xor_sync(0xffffffffu, sum, 2);
        if (sub == 0) s_inv[q] = 1.f / sum;
    }
    __syncthreads();

    // ---- phase 2: O[q][d] = sum_j P[q][j]*V[j][d]; warp tile 16 x 32 ----
    {
        const int wm = (wid & 3) * 16;
        const int wn = (wid >> 2) * 32;
        float acc[4][4] = {};
#pragma unroll
        for (int kk = 0; kk < 192; kk += 8) {
            uint32_t a[4];
            a[0] = __float_as_uint(Ss[(wm + gq    ) * VSS + kk + tg    ]);
            a[1] = __float_as_uint(Ss[(wm + gq + 8) * VSS + kk + tg    ]);
            a[2] = __float_as_uint(Ss[(wm + gq    ) * VSS + kk + tg + 4]);
            a[3] = __float_as_uint(Ss[(wm + gq + 8) * VSS + kk + tg + 4]);
#pragma unroll
            for (int nt = 0; nt < 4; ++nt) {
                const int n = wn + nt * 8 + gq;      // n = d index
                uint32_t b[2];
                b[0] = __float_as_uint(Vt[n * VSS + kk + tg    ]);
                b[1] = __float_as_uint(Vt[n * VSS + kk + tg + 4]);
                mma_tf32(acc[nt], a, b);
            }
        }
        const int qa = wm + gq;
        const float inv0 = s_inv[qa];
        const float inv1 = s_inv[qa + 8];
#pragma unroll
        for (int nt = 0; nt < 4; ++nt) {
            const int d = wn + nt * 8 + 2 * tg;
            float2 s0 = {acc[nt][0] * inv0, acc[nt][1] * inv0};
            float2 s1 = {acc[nt][2] * inv1, acc[nt][3] * inv1};
            *(float2*)&g_attn[(size_t)(q0 + qa    ) * DM + c0 + d] = s0;
            *(float2*)&g_attn[(size_t)(q0 + qa + 8) * DM + c0 + d] = s1;
        }
    }
}

// ---------------- launch ----------------
extern "C" void kernel_launch(void* const* d_in, const int* in_sizes, int n_in,
                              void* d_out, int out_size)
{
    const float* q  = (const float*)d_in[0];
    const float* k  = (const float*)d_in[1];
    const float* v  = (const float*)d_in[2];
    const float* Wq = (const float*)d_in[3];
    const float* bq = (const float*)d_in[4];
    const float* Wk = (const float*)d_in[5];
    const float* bk = (const float*)d_in[6];
    const float* Wv = (const float*)d_in[7];
    const float* bv = (const float*)d_in[8];
    const float* Wo = (const float*)d_in[9];
    const float* bo = (const float*)d_in[10];
    float* out = (float*)d_out;

    cudaFuncSetAttribute(qkv_proj_kernel,
                         cudaFuncAttributeMaxDynamicSharedMemorySize, GEMM_SMEM);
    cudaFuncSetAttribute(out_proj_kernel,
                         cudaFuncAttributeMaxDynamicSharedMemorySize, GEMM_SMEM);
    cudaFuncSetAttribute(attn_kernel,
                         cudaFuncAttributeMaxDynamicSharedMemorySize, ATT_SMEM_BYTES);

    qkv_proj_kernel<<<dim3(L / BMM, DM / BMM, 3), 256, GEMM_SMEM>>>(q, k, v, Wq, Wk, Wv, bq, bk, bv);
    attn_kernel<<<dim3(L / 64, NH), 256, ATT_SMEM_BYTES>>>();
    out_proj_kernel<<<dim3(L / BMM, DM / BMM), 256, GEMM_SMEM>>>(Wo, bo, out);
}

// round 6
// speedup vs baseline: 3.5540x; 1.2639x over previous
#include <cuda_runtime.h>
#include <cuda_fp16.h>
#include <cstdint>

#define L    4096
#define DM   768
#define NH   12
#define HD   64
#define ATTN_SCALE 0.125f   // 1/sqrt(64)

// ---------------- scratch (no allocations allowed) ----------------
__device__ float g_Q[L * DM];        // row-major [i][h*64+d]
__device__ float g_K[L * DM];
__device__ float g_V[L * DM];
__device__ float g_attn[L * DM];     // [i][h*64+d]

// =======================================================================
// helpers
// =======================================================================
__device__ __forceinline__ uint32_t f2h2(float lo, float hi) {
    __half2 h = __floats2half2_rn(lo, hi);
    return *(uint32_t*)&h;
}

__device__ __forceinline__ void mma_f16(float c[4], const uint32_t a[4], const uint32_t b[2]) {
    asm volatile(
        "mma.sync.aligned.m16n8k16.row.col.f32.f16.f16.f32 "
        "{%0,%1,%2,%3}, {%4,%5,%6,%7}, {%8,%9}, {%0,%1,%2,%3};"
        : "+f"(c[0]), "+f"(c[1]), "+f"(c[2]), "+f"(c[3])
        : "r"(a[0]), "r"(a[1]), "r"(a[2]), "r"(a[3]), "r"(b[0]), "r"(b[1]));
}

// =======================================================================
// fp16 tensor-core GEMM: C[i,j] = sum_k X[i,k]*W[j,k] + b[j]
// CTA 128x128, BK=32, 256 threads (8 warps, 4x2), warp tile 32x64.
// smem half tiles, row stride 40 halfs (conflict-free fragment LDS).
// =======================================================================
#define BMM 128
#define BKT 32
#define SSH 40                               // row stride in halfs
#define BUFH (BMM * SSH)                     // 5120 halfs per buffer
#define GEMM_SMEM (4 * BUFH * 2)             // A0,B0,A1,B1 = 40960 bytes

__device__ __forceinline__ void g2r(const float* __restrict__ src, int row0, int kt,
                                    int tid, float4 r[4]) {
#pragma unroll
    for (int i = 0; i < 4; ++i) {
        const int f = tid + i * 256;         // 0..1023
        const int r_ = f >> 3;               // 0..127
        const int c_ = f & 7;                // 0..7
        r[i] = *(const float4*)&src[(size_t)(row0 + r_) * DM + kt * BKT + c_ * 4];
    }
}
__device__ __forceinline__ void r2s(__half* __restrict__ dst, int tid, const float4 r[4]) {
#pragma unroll
    for (int i = 0; i < 4; ++i) {
        const int f = tid + i * 256;
        const int r_ = f >> 3;
        const int c_ = f & 7;
        uint2 u;
        u.x = f2h2(r[i].x, r[i].y);
        u.y = f2h2(r[i].z, r[i].w);
        *(uint2*)&dst[r_ * SSH + c_ * 4] = u;
    }
}

__device__ __forceinline__ void gemm_mma_body(const float* __restrict__ X,
                                              const float* __restrict__ W,
                                              const float* __restrict__ Bb,
                                              float* __restrict__ C,
                                              int i0, int j0)
{
    extern __shared__ __half smh[];
    __half* As = smh;                         // [2][BUFH]
    __half* Bs = smh + 2 * BUFH;

    const int tid  = threadIdx.x;
    const int wid  = tid >> 5;
    const int lane = tid & 31;
    const int gq   = lane >> 2;               // 0..7
    const int tg   = lane & 3;                // 0..3
    const int wm0  = (wid & 3) * 32;
    const int wn0  = (wid >> 2) * 64;

    float acc[2][8][4] = {};
    float4 areg[4], breg[4];

    g2r(X, i0, 0, tid, areg);
    g2r(W, j0, 0, tid, breg);
    r2s(As, tid, areg);
    r2s(Bs, tid, breg);
    __syncthreads();

#define NCHUNK (DM / BKT)                     // 24
    for (int kt = 0; kt < NCHUNK; ++kt) {
        const int cur = kt & 1;
        const int nxt = cur ^ 1;
        const bool more = (kt + 1 < NCHUNK);
        if (more) {
            g2r(X, i0, kt + 1, tid, areg);
            g2r(W, j0, kt + 1, tid, breg);
        }
        const __half* Ac = As + cur * BUFH;
        const __half* Bc = Bs + cur * BUFH;

#pragma unroll
        for (int kk = 0; kk < BKT; kk += 16) {
            uint32_t af[2][4], bf[8][2];
#pragma unroll
            for (int mt = 0; mt < 2; ++mt) {
                const int r = wm0 + mt * 16 + gq;
                af[mt][0] = *(const uint32_t*)&Ac[(r    ) * SSH + kk + 2 * tg    ];
                af[mt][1] = *(const uint32_t*)&Ac[(r + 8) * SSH + kk + 2 * tg    ];
                af[mt][2] = *(const uint32_t*)&Ac[(r    ) * SSH + kk + 2 * tg + 8];
                af[mt][3] = *(const uint32_t*)&Ac[(r + 8) * SSH + kk + 2 * tg + 8];
            }
#pragma unroll
            for (int nt = 0; nt < 8; ++nt) {
                const int n = wn0 + nt * 8 + gq;
                bf[nt][0] = *(const uint32_t*)&Bc[n * SSH + kk + 2 * tg    ];
                bf[nt][1] = *(const uint32_t*)&Bc[n * SSH + kk + 2 * tg + 8];
            }
#pragma unroll
            for (int mt = 0; mt < 2; ++mt)
#pragma unroll
                for (int nt = 0; nt < 8; ++nt)
                    mma_f16(acc[mt][nt], af[mt], bf[nt]);
        }

        if (more) {
            r2s(As + nxt * BUFH, tid, areg);
            r2s(Bs + nxt * BUFH, tid, breg);
        }
        __syncthreads();
    }

#pragma unroll
    for (int nt = 0; nt < 8; ++nt) {
        const int col = j0 + wn0 + nt * 8 + 2 * tg;
        const float2 bb = *(const float2*)&Bb[col];
#pragma unroll
        for (int mt = 0; mt < 2; ++mt) {
            const int r = i0 + wm0 + mt * 16 + gq;
            float2 s0 = {acc[mt][nt][0] + bb.x, acc[mt][nt][1] + bb.y};
            float2 s1 = {acc[mt][nt][2] + bb.x, acc[mt][nt][3] + bb.y};
            *(float2*)&C[(size_t)r * DM + col] = s0;
            *(float2*)&C[(size_t)(r + 8) * DM + col] = s1;
        }
    }
}

__global__ void __launch_bounds__(256)
qkv_proj_kernel(const float* __restrict__ xq, const float* __restrict__ xk, const float* __restrict__ xv,
                const float* __restrict__ wq, const float* __restrict__ wk, const float* __restrict__ wv,
                const float* __restrict__ bq, const float* __restrict__ bk, const float* __restrict__ bv)
{
    const int z = blockIdx.z;
    const float* X  = (z == 0) ? xq : (z == 1) ? xk : xv;
    const float* W  = (z == 0) ? wq : (z == 1) ? wk : wv;
    const float* Bb = (z == 0) ? bq : (z == 1) ? bk : bv;
    float* dst      = (z == 0) ? g_Q : (z == 1) ? g_K : g_V;
    gemm_mma_body(X, W, Bb, dst, blockIdx.x * BMM, blockIdx.y * BMM);
}

__global__ void __launch_bounds__(256)
out_proj_kernel(const float* __restrict__ W, const float* __restrict__ Bb,
                float* __restrict__ out)
{
    gemm_mma_body(g_attn, W, Bb, out, blockIdx.x * BMM, blockIdx.y * BMM);
}

// =======================================================================
// sliding-window attention with fp16 MMA
// One block per (64-query tile, head). Keys [q0-64, q0+127] -> 192 rows.
// half strides: Qs/Ks 72, Vt/Ps 200; Ss fp32 stride 196.
// =======================================================================
#define QKH 72
#define VPH 200
#define SSF 196
// byte offsets within dynamic smem:
#define OFF_QS 0                              // 64*72 halfs  = 9216 B
#define OFF_KS (OFF_QS + 64 * QKH * 2)        // 192*72 halfs = 27648 B
#define OFF_VT (OFF_KS + 192 * QKH * 2)       // 64*200 halfs = 25600 B
#define OFF_PS (OFF_VT + 64 * VPH * 2)        // 64*200 halfs = 25600 B
#define OFF_SS (OFF_PS + 64 * VPH * 2)        // 64*196 f32   = 50176 B
#define ATT_SMEM_BYTES (OFF_SS + 64 * SSF * 4)

__global__ void __launch_bounds__(256)
attn_kernel()
{
    extern __shared__ char smc[];
    __half* Qs = (__half*)(smc + OFF_QS);     // [q][d]
    __half* Ks = (__half*)(smc + OFF_KS);     // [j][d]
    __half* Vt = (__half*)(smc + OFF_VT);     // [d][j]
    __half* Ps = (__half*)(smc + OFF_PS);     // [q][j]
    float*  Ss = (float*)(smc + OFF_SS);      // [q][j]
    __shared__ float s_inv[64];

    const int tid  = threadIdx.x;
    const int q0   = blockIdx.x * 64;
    const int h    = blockIdx.y;
    const int c0   = h * HD;
    const int wid  = tid >> 5;
    const int lane = tid & 31;
    const int gq   = lane >> 2;
    const int tg   = lane & 3;

    // ---- stage Q ----
    for (int idx = tid; idx < 64 * 16; idx += 256) {
        const int q = idx >> 4, c4 = idx & 15;
        const float4 v = *(const float4*)&g_Q[(size_t)(q0 + q) * DM + c0 + c4 * 4];
        uint2 u = {f2h2(v.x, v.y), f2h2(v.z, v.w)};
        *(uint2*)&Qs[q * QKH + c4 * 4] = u;
    }
    // ---- stage K (clamped rows; masked in softmax) ----
    for (int idx = tid; idx < 192 * 16; idx += 256) {
        const int j = idx >> 4, c4 = idx & 15;
        const int jg = min(max(q0 - 64 + j, 0), L - 1);
        const float4 v = *(const float4*)&g_K[(size_t)jg * DM + c0 + c4 * 4];
        uint2 u = {f2h2(v.x, v.y), f2h2(v.z, v.w)};
        *(uint2*)&Ks[j * QKH + c4 * 4] = u;
    }
    // ---- stage V transposed: Vt[d][j] ----
    for (int idx = tid; idx < 192 * 16; idx += 256) {
        const int j = idx >> 4, c4 = idx & 15;
        const int jg = min(max(q0 - 64 + j, 0), L - 1);
        const float4 v = *(const float4*)&g_V[(size_t)jg * DM + c0 + c4 * 4];
        Vt[(c4 * 4 + 0) * VPH + j] = __float2half_rn(v.x);
        Vt[(c4 * 4 + 1) * VPH + j] = __float2half_rn(v.y);
        Vt[(c4 * 4 + 2) * VPH + j] = __float2half_rn(v.z);
        Vt[(c4 * 4 + 3) * VPH + j] = __float2half_rn(v.w);
    }
    __syncthreads();

    // ---- phase 1: S[q][j] = sum_d Q[q][d]*K[j][d]; warp tile 16 x 96 ----
    {
        const int wm = (wid & 3) * 16;
        const int wn = (wid >> 2) * 96;
        float acc[12][4] = {};
#pragma unroll
        for (int kk = 0; kk < 64; kk += 16) {
            uint32_t a[4];
            a[0] = *(const uint32_t*)&Qs[(wm + gq    ) * QKH + kk + 2 * tg    ];
            a[1] = *(const uint32_t*)&Qs[(wm + gq + 8) * QKH + kk + 2 * tg    ];
            a[2] = *(const uint32_t*)&Qs[(wm + gq    ) * QKH + kk + 2 * tg + 8];
            a[3] = *(const uint32_t*)&Qs[(wm + gq + 8) * QKH + kk + 2 * tg + 8];
#pragma unroll
            for (int nt = 0; nt < 12; ++nt) {
                const int n = wn + nt * 8 + gq;
                uint32_t b[2];
                b[0] = *(const uint32_t*)&Ks[n * QKH + kk + 2 * tg    ];
                b[1] = *(const uint32_t*)&Ks[n * QKH + kk + 2 * tg + 8];
                mma_f16(acc[nt], a, b);
            }
        }
#pragma unroll
        for (int nt = 0; nt < 12; ++nt) {
            const int col = wn + nt * 8 + 2 * tg;
            float2 s0 = {acc[nt][0], acc[nt][1]};
            float2 s1 = {acc[nt][2], acc[nt][3]};
            *(float2*)&Ss[(wm + gq    ) * SSF + col] = s0;
            *(float2*)&Ss[(wm + gq + 8) * SSF + col] = s1;
        }
    }
    __syncthreads();

    // ---- masked softmax over j for each q (4 threads per query) ----
    {
        const int q   = tid >> 2;
        const int sub = tid & 3;
        const int jlo = max(q, 64 - q0);
        const int jhi = min(q + 128, (L - 1) - (q0 - 64));
        float mx = -1e30f;
        for (int j = jlo + sub; j <= jhi; j += 4)
            mx = fmaxf(mx, Ss[q * SSF + j]);
        mx = fmaxf(mx, __shfl_xor_sync(0xffffffffu, mx, 1));
        mx = fmaxf(mx, __shfl_xor_sync(0xffffffffu, mx, 2));
        float sum = 0.f;
        for (int j = sub; j < 192; j += 4) {
            float p = 0.f;
            if (j >= jlo && j <= jhi) {
                const __half ph = __float2half_rn(__expf((Ss[q * SSF + j] - mx) * ATTN_SCALE));
                p = __half2float(ph);
            }
            sum += p;
            Ps[q * VPH + j] = __float2half_rn(p);
        }
        sum += __shfl_xor_sync(0xffffffffu, sum, 1);
        sum += __shfl_xor_sync(0xffffffffu, sum, 2);
        if (sub == 0) s_inv[q] = 1.f / sum;
    }
    __syncthreads();

    // ---- phase 2: O[q][d] = sum_j P[q][j]*V[j][d]; warp tile 16 x 32 ----
    {
        const int wm = (wid & 3) * 16;
        const int wn = (wid >> 2) * 32;
        float acc[4][4] = {};
#pragma unroll
        for (int kk = 0; kk < 192; kk += 16) {
            uint32_t a[4];
            a[0] = *(const uint32_t*)&Ps[(wm + gq    ) * VPH + kk + 2 * tg    ];
            a[1] = *(const uint32_t*)&Ps[(wm + gq + 8) * VPH + kk + 2 * tg    ];
            a[2] = *(const uint32_t*)&Ps[(wm + gq    ) * VPH + kk + 2 * tg + 8];
            a[3] = *(const uint32_t*)&Ps[(wm + gq + 8) * VPH + kk + 2 * tg + 8];
#pragma unroll
            for (int nt = 0; nt < 4; ++nt) {
                const int n = wn + nt * 8 + gq;       // n = d index
                uint32_t b[2];
                b[0] = *(const uint32_t*)&Vt[n * VPH + kk + 2 * tg    ];
                b[1] = *(const uint32_t*)&Vt[n * VPH + kk + 2 * tg + 8];
                mma_f16(acc[nt], a, b);
            }
        }
        const int qa = wm + gq;
        const float inv0 = s_inv[qa];
        const float inv1 = s_inv[qa + 8];
#pragma unroll
        for (int nt = 0; nt < 4; ++nt) {
            const int d = wn + nt * 8 + 2 * tg;
            float2 s0 = {acc[nt][0] * inv0, acc[nt][1] * inv0};
            float2 s1 = {acc[nt][2] * inv1, acc[nt][3] * inv1};
            *(float2*)&g_attn[(size_t)(q0 + qa    ) * DM + c0 + d] = s0;
            *(float2*)&g_attn[(size_t)(q0 + qa + 8) * DM + c0 + d] = s1;
        }
    }
}

// ---------------- launch ----------------
extern "C" void kernel_launch(void* const* d_in, const int* in_sizes, int n_in,
                              void* d_out, int out_size)
{
    const float* q  = (const float*)d_in[0];
    const float* k  = (const float*)d_in[1];
    const float* v  = (const float*)d_in[2];
    const float* Wq = (const float*)d_in[3];
    const float* bq = (const float*)d_in[4];
    const float* Wk = (const float*)d_in[5];
    const float* bk = (const float*)d_in[6];
    const float* Wv = (const float*)d_in[7];
    const float* bv = (const float*)d_in[8];
    const float* Wo = (const float*)d_in[9];
    const float* bo = (const float*)d_in[10];
    float* out = (float*)d_out;

    cudaFuncSetAttribute(qkv_proj_kernel,
                         cudaFuncAttributeMaxDynamicSharedMemorySize, GEMM_SMEM);
    cudaFuncSetAttribute(out_proj_kernel,
                         cudaFuncAttributeMaxDynamicSharedMemorySize, GEMM_SMEM);
    cudaFuncSetAttribute(attn_kernel,
                         cudaFuncAttributeMaxDynamicSharedMemorySize, ATT_SMEM_BYTES);

    qkv_proj_kernel<<<dim3(L / BMM, DM / BMM, 3), 256, GEMM_SMEM>>>(q, k, v, Wq, Wk, Wv, bq, bk, bv);
    attn_kernel<<<dim3(L / 64, NH), 256, ATT_SMEM_BYTES>>>();
    out_proj_kernel<<<dim3(L / BMM, DM / BMM), 256, GEMM_SMEM>>>(Wo, bo, out);
}

// round 7
// speedup vs baseline: 5.7262x; 1.6112x over previous
#include <cuda_runtime.h>
#include <cuda_fp16.h>
#include <cstdint>

#define L    4096
#define DM   768
#define NH   12
#define HD   64
#define ATTN_SCALE 0.125f   // 1/sqrt(64)

// ---------------- scratch (no allocations allowed) ----------------
__device__ __align__(16) __half g_Xh[3][L * DM];   // packed inputs (q,k,v streams)
__device__ __align__(16) __half g_Wh[4][DM * DM];  // packed Wq,Wk,Wv,Wo
__device__ __align__(16) __half g_Qh[L * DM];
__device__ __align__(16) __half g_Kh[L * DM];
__device__ __align__(16) __half g_Vh[L * DM];
__device__ __align__(16) __half g_Ah[L * DM];      // attention output (half)

// =======================================================================
// helpers
// =======================================================================
__device__ __forceinline__ uint32_t f2h2(float lo, float hi) {
    __half2 h = __floats2half2_rn(lo, hi);
    return *(uint32_t*)&h;
}
__device__ __forceinline__ void mma_f16(float c[4], const uint32_t a[4], const uint32_t b[2]) {
    asm volatile(
        "mma.sync.aligned.m16n8k16.row.col.f32.f16.f16.f32 "
        "{%0,%1,%2,%3}, {%4,%5,%6,%7}, {%8,%9}, {%0,%1,%2,%3};"
        : "+f"(c[0]), "+f"(c[1]), "+f"(c[2]), "+f"(c[3])
        : "r"(a[0]), "r"(a[1]), "r"(a[2]), "r"(a[3]), "r"(b[0]), "r"(b[1]));
}
__device__ __forceinline__ void cp16(uint32_t sdst, const void* gsrc) {
    asm volatile("cp.async.cg.shared.global [%0], [%1], 16;" :: "r"(sdst), "l"(gsrc));
}
#define CP_COMMIT() asm volatile("cp.async.commit_group;" ::: "memory")
#define CP_WAIT1()  asm volatile("cp.async.wait_group 1;" ::: "memory")
#define CP_WAIT0()  asm volatile("cp.async.wait_group 0;" ::: "memory")

// =======================================================================
// pack kernel: fp32 -> fp16 for X (3x L*DM) and W (4x DM*DM)
// =======================================================================
#define X4 (L * DM / 4)     // 786432 float4s per X tensor
#define W4 (DM * DM / 4)    // 147456 per W
#define PACK_TOTAL (3 * X4 + 4 * W4)
#define PACK_BLOCKS (PACK_TOTAL / 256)

__global__ void __launch_bounds__(256)
pack_kernel(const float* __restrict__ xq, const float* __restrict__ xk, const float* __restrict__ xv,
            const float* __restrict__ wq, const float* __restrict__ wk, const float* __restrict__ wv,
            const float* __restrict__ wo)
{
    const int idx = blockIdx.x * 256 + threadIdx.x;
    float4 v;
    __half* dst;
    if (idx < 3 * X4) {
        const int z = idx / X4;
        const int r = idx - z * X4;
        const float* s = (z == 0) ? xq : (z == 1) ? xk : xv;
        v = ((const float4*)s)[r];
        dst = &g_Xh[z][r * 4];
    } else {
        const int t = idx - 3 * X4;
        const int z = t / W4;
        const int r = t - z * W4;
        const float* s = (z == 0) ? wq : (z == 1) ? wk : (z == 2) ? wv : wo;
        v = ((const float4*)s)[r];
        dst = &g_Wh[z][r * 4];
    }
    uint2 u = {f2h2(v.x, v.y), f2h2(v.z, v.w)};
    *(uint2*)dst = u;
}

// =======================================================================
// fp16 GEMM with cp.async: C[i,j] = sum_k A[i,k]*B[j,k] + bias[j]
// CTA 128x128, BK=64 halfs, 256 threads (8 warps 4x2), warp tile 32x64.
// =======================================================================
#define BMM 128
#define BKH 64
#define SSH 72                                // row stride (halfs); 144B, 16B-mult
#define BUFH (BMM * SSH)                      // 9216 halfs per buffer
#define GEMM_SMEM (4 * BUFH * 2)              // A0,A1,B0,B1 = 73728 bytes
#define NT (DM / BKH)                         // 12

__device__ __forceinline__ void stage_tile(uint32_t sdst, const __half* __restrict__ src,
                                           int row0, int kt, int tid)
{
#pragma unroll
    for (int i = 0; i < 4; ++i) {
        const int f  = tid + i * 256;         // 0..1023
        const int r  = f >> 3;                // 0..127
        const int c  = f & 7;                 // 0..7 (16B chunks)
        cp16(sdst + (uint32_t)(r * SSH + c * 8) * 2,
             src + (size_t)(row0 + r) * DM + kt * BKH + c * 8);
    }
}

template <bool OUTF32>
__device__ __forceinline__ void gemm_h(const __half* __restrict__ A,
                                       const __half* __restrict__ B,
                                       const float* __restrict__ bias,
                                       void* __restrict__ Cout,
                                       int i0, int j0)
{
    extern __shared__ __half smh[];
    __half* As = smh;                          // [2][BUFH]
    __half* Bs = smh + 2 * BUFH;
    const uint32_t sA = (uint32_t)__cvta_generic_to_shared(As);
    const uint32_t sB = (uint32_t)__cvta_generic_to_shared(Bs);

    const int tid  = threadIdx.x;
    const int wid  = tid >> 5;
    const int lane = tid & 31;
    const int gq   = lane >> 2;
    const int tg   = lane & 3;
    const int wm0  = (wid & 3) * 32;
    const int wn0  = (wid >> 2) * 64;

    float acc[2][8][4] = {};

    stage_tile(sA, A, i0, 0, tid);
    stage_tile(sB, B, j0, 0, tid);
    CP_COMMIT();

    for (int kt = 0; kt < NT; ++kt) {
        const int cur = kt & 1;
        const bool more = (kt + 1 < NT);
        if (more) {
            const int nxt = cur ^ 1;
            stage_tile(sA + nxt * BUFH * 2, A, i0, kt + 1, tid);
            stage_tile(sB + nxt * BUFH * 2, B, j0, kt + 1, tid);
            CP_COMMIT();
            CP_WAIT1();
        } else {
            CP_WAIT0();
        }
        __syncthreads();

        const __half* Ac = As + cur * BUFH;
        const __half* Bc = Bs + cur * BUFH;
#pragma unroll
        for (int kk = 0; kk < BKH; kk += 16) {
            uint32_t af[2][4], bf[8][2];
#pragma unroll
            for (int mt = 0; mt < 2; ++mt) {
                const int r = wm0 + mt * 16 + gq;
                af[mt][0] = *(const uint32_t*)&Ac[(r    ) * SSH + kk + 2 * tg    ];
                af[mt][1] = *(const uint32_t*)&Ac[(r + 8) * SSH + kk + 2 * tg    ];
                af[mt][2] = *(const uint32_t*)&Ac[(r    ) * SSH + kk + 2 * tg + 8];
                af[mt][3] = *(const uint32_t*)&Ac[(r + 8) * SSH + kk + 2 * tg + 8];
            }
#pragma unroll
            for (int nt = 0; nt < 8; ++nt) {
                const int n = wn0 + nt * 8 + gq;
                bf[nt][0] = *(const uint32_t*)&Bc[n * SSH + kk + 2 * tg    ];
                bf[nt][1] = *(const uint32_t*)&Bc[n * SSH + kk + 2 * tg + 8];
            }
#pragma unroll
            for (int mt = 0; mt < 2; ++mt)
#pragma unroll
                for (int nt = 0; nt < 8; ++nt)
                    mma_f16(acc[mt][nt], af[mt], bf[nt]);
        }
        __syncthreads();
    }

#pragma unroll
    for (int nt = 0; nt < 8; ++nt) {
        const int col = j0 + wn0 + nt * 8 + 2 * tg;
        const float2 bb = *(const float2*)&bias[col];
#pragma unroll
        for (int mt = 0; mt < 2; ++mt) {
            const int r = i0 + wm0 + mt * 16 + gq;
            if (OUTF32) {
                float* C = (float*)Cout;
                float2 s0 = {acc[mt][nt][0] + bb.x, acc[mt][nt][1] + bb.y};
                float2 s1 = {acc[mt][nt][2] + bb.x, acc[mt][nt][3] + bb.y};
                *(float2*)&C[(size_t)r * DM + col] = s0;
                *(float2*)&C[(size_t)(r + 8) * DM + col] = s1;
            } else {
                __half* C = (__half*)Cout;
                uint32_t h0 = f2h2(acc[mt][nt][0] + bb.x, acc[mt][nt][1] + bb.y);
                uint32_t h1 = f2h2(acc[mt][nt][2] + bb.x, acc[mt][nt][3] + bb.y);
                *(uint32_t*)&C[(size_t)r * DM + col] = h0;
                *(uint32_t*)&C[(size_t)(r + 8) * DM + col] = h1;
            }
        }
    }
}

__global__ void __launch_bounds__(256, 2)
qkv_proj_kernel(const float* __restrict__ bq, const float* __restrict__ bk,
                const float* __restrict__ bv)
{
    const int z = blockIdx.z;
    const float* Bb = (z == 0) ? bq : (z == 1) ? bk : bv;
    __half* dst     = (z == 0) ? g_Qh : (z == 1) ? g_Kh : g_Vh;
    gemm_h<false>(g_Xh[z], g_Wh[z], Bb, dst, blockIdx.x * BMM, blockIdx.y * BMM);
}

__global__ void __launch_bounds__(256, 2)
out_proj_kernel(const float* __restrict__ bo, float* __restrict__ out)
{
    gemm_h<true>(g_Ah, g_Wh[3], bo, out, blockIdx.x * BMM, blockIdx.y * BMM);
}

// =======================================================================
// sliding-window attention, fp16 MMA + cp.async staging
// One block per (64-query tile, head). Keys [q0-64, q0+127] -> 192 rows.
// smem layout (bytes):
//   [0, 36864)  Qs(64x72h @0) + Ks(192x72h @9216); ALIASED by Ps(64x200h @0)
//   [36864, 62464)  Vt 64x200 halfs
//   [62464, 112640) Ss 64x196 fp32
// =======================================================================
#define QKH 72
#define VPH 200
#define SSF 196
#define OFF_QS 0
#define OFF_KS 9216
#define OFF_PS 0
#define OFF_VT 36864
#define OFF_SS 62464
#define ATT_SMEM_BYTES (OFF_SS + 64 * SSF * 4)   // 112640

__global__ void __launch_bounds__(256, 2)
attn_kernel()
{
    extern __shared__ char smc[];
    __half* Qs = (__half*)(smc + OFF_QS);
    __half* Ks = (__half*)(smc + OFF_KS);
    __half* Vt = (__half*)(smc + OFF_VT);
    __half* Ps = (__half*)(smc + OFF_PS);
    float*  Ss = (float*)(smc + OFF_SS);
    __shared__ float s_inv[64];

    const int tid  = threadIdx.x;
    const int q0   = blockIdx.x * 64;
    const int h    = blockIdx.y;
    const int c0   = h * HD;
    const int wid  = tid >> 5;
    const int lane = tid & 31;
    const int gq   = lane >> 2;
    const int tg   = lane & 3;

    // ---- async stage Q (64 rows x 8 chunks) and K (192 x 8) ----
    {
        const uint32_t sQ = (uint32_t)__cvta_generic_to_shared(Qs);
        const uint32_t sK = (uint32_t)__cvta_generic_to_shared(Ks);
#pragma unroll
        for (int i = 0; i < 2; ++i) {
            const int f = tid + i * 256;
            const int q = f >> 3, c = f & 7;
            cp16(sQ + (uint32_t)(q * QKH + c * 8) * 2,
                 g_Qh + (size_t)(q0 + q) * DM + c0 + c * 8);
        }
#pragma unroll
        for (int i = 0; i < 6; ++i) {
            const int f = tid + i * 256;
            const int j = f >> 3, c = f & 7;
            const int jg = min(max(q0 - 64 + j, 0), L - 1);
            cp16(sK + (uint32_t)(j * QKH + c * 8) * 2,
                 g_Kh + (size_t)jg * DM + c0 + c * 8);
        }
        CP_COMMIT();
    }
    // ---- V transpose (sync loads overlap with async Q/K) ----
    for (int idx = tid; idx < 192 * 32; idx += 256) {
        const int j  = idx >> 5;
        const int dp = idx & 31;
        const int jg = min(max(q0 - 64 + j, 0), L - 1);
        const __half2 hv = *(const __half2*)&g_Vh[(size_t)jg * DM + c0 + dp * 2];
        Vt[(dp * 2    ) * VPH + j] = __low2half(hv);
        Vt[(dp * 2 + 1) * VPH + j] = __high2half(hv);
    }
    CP_WAIT0();
    __syncthreads();

    // ---- phase 1: S[q][j] = sum_d Q[q][d]*K[j][d]; warp tile 16 x 96 ----
    {
        const int wm = (wid & 3) * 16;
        const int wn = (wid >> 2) * 96;
        float acc[12][4] = {};
#pragma unroll
        for (int kk = 0; kk < 64; kk += 16) {
            uint32_t a[4];
            a[0] = *(const uint32_t*)&Qs[(wm + gq    ) * QKH + kk + 2 * tg    ];
            a[1] = *(const uint32_t*)&Qs[(wm + gq + 8) * QKH + kk + 2 * tg    ];
            a[2] = *(const uint32_t*)&Qs[(wm + gq    ) * QKH + kk + 2 * tg + 8];
            a[3] = *(const uint32_t*)&Qs[(wm + gq + 8) * QKH + kk + 2 * tg + 8];
#pragma unroll
            for (int nt = 0; nt < 12; ++nt) {
                const int n = wn + nt * 8 + gq;
                uint32_t b[2];
                b[0] = *(const uint32_t*)&Ks[n * QKH + kk + 2 * tg    ];
                b[1] = *(const uint32_t*)&Ks[n * QKH + kk + 2 * tg + 8];
                mma_f16(acc[nt], a, b);
            }
        }
#pragma unroll
        for (int nt = 0; nt < 12; ++nt) {
            const int col = wn + nt * 8 + 2 * tg;
            float2 s0 = {acc[nt][0], acc[nt][1]};
            float2 s1 = {acc[nt][2], acc[nt][3]};
            *(float2*)&Ss[(wm + gq    ) * SSF + col] = s0;
            *(float2*)&Ss[(wm + gq + 8) * SSF + col] = s1;
        }
    }
    __syncthreads();   // Qs/Ks dead past here; Ps may overwrite them

    // ---- masked softmax over j (4 threads per query); P -> half ----
    {
        const int q   = tid >> 2;
        const int sub = tid & 3;
        const int jlo = max(q, 64 - q0);
        const int jhi = min(q + 128, (L - 1) - (q0 - 64));
        float mx = -1e30f;
        for (int j = jlo + sub; j <= jhi; j += 4)
            mx = fmaxf(mx, Ss[q * SSF + j]);
        mx = fmaxf(mx, __shfl_xor_sync(0xffffffffu, mx, 1));
        mx = fmaxf(mx, __shfl_xor_sync(0xffffffffu, mx, 2));
        float sum = 0.f;
        for (int j = sub; j < 192; j += 4) {
            float p = 0.f;
            if (j >= jlo && j <= jhi) {
                const __half ph = __float2half_rn(__expf((Ss[q * SSF + j] - mx) * ATTN_SCALE));
                p = __half2float(ph);
            }
            sum += p;
            Ps[q * VPH + j] = __float2half_rn(p);
        }
        sum += __shfl_xor_sync(0xffffffffu, sum, 1);
        sum += __shfl_xor_sync(0xffffffffu, sum, 2);
        if (sub == 0) s_inv[q] = 1.f / sum;
    }
    __syncthreads();

    // ---- phase 2: O[q][d] = sum_j P[q][j]*V[j][d]; warp tile 16 x 32 ----
    {
        const int wm = (wid & 3) * 16;
        const int wn = (wid >> 2) * 32;
        float acc[4][4] = {};
#pragma unroll
        for (int kk = 0; kk < 192; kk += 16) {
            uint32_t a[4];
            a[0] = *(const uint32_t*)&Ps[(wm + gq    ) * VPH + kk + 2 * tg    ];
            a[1] = *(const uint32_t*)&Ps[(wm + gq + 8) * VPH + kk + 2 * tg    ];
            a[2] = *(const uint32_t*)&Ps[(wm + gq    ) * VPH + kk + 2 * tg + 8];
            a[3] = *(const uint32_t*)&Ps[(wm + gq + 8) * VPH + kk + 2 * tg + 8];
#pragma unroll
            for (int nt = 0; nt < 4; ++nt) {
                const int n = wn + nt * 8 + gq;       // n = d index
                uint32_t b[2];
                b[0] = *(const uint32_t*)&Vt[n * VPH + kk + 2 * tg    ];
                b[1] = *(const uint32_t*)&Vt[n * VPH + kk + 2 * tg + 8];
                mma_f16(acc[nt], a, b);
            }
        }
        const int qa = wm + gq;
        const float inv0 = s_inv[qa];
        const float inv1 = s_inv[qa + 8];
#pragma unroll
        for (int nt = 0; nt < 4; ++nt) {
            const int d = wn + nt * 8 + 2 * tg;
            uint32_t h0 = f2h2(acc[nt][0] * inv0, acc[nt][1] * inv0);
            uint32_t h1 = f2h2(acc[nt][2] * inv1, acc[nt][3] * inv1);
            *(uint32_t*)&g_Ah[(size_t)(q0 + qa    ) * DM + c0 + d] = h0;
            *(uint32_t*)&g_Ah[(size_t)(q0 + qa + 8) * DM + c0 + d] = h1;
        }
    }
}

// ---------------- launch ----------------
extern "C" void kernel_launch(void* const* d_in, const int* in_sizes, int n_in,
                              void* d_out, int out_size)
{
    const float* q  = (const float*)d_in[0];
    const float* k  = (const float*)d_in[1];
    const float* v  = (const float*)d_in[2];
    const float* Wq = (const float*)d_in[3];
    const float* bq = (const float*)d_in[4];
    const float* Wk = (const float*)d_in[5];
    const float* bk = (const float*)d_in[6];
    const float* Wv = (const float*)d_in[7];
    const float* bv = (const float*)d_in[8];
    const float* Wo = (const float*)d_in[9];
    const float* bo = (const float*)d_in[10];
    float* out = (float*)d_out;

    cudaFuncSetAttribute(qkv_proj_kernel,
                         cudaFuncAttributeMaxDynamicSharedMemorySize, GEMM_SMEM);
    cudaFuncSetAttribute(out_proj_kernel,
                         cudaFuncAttributeMaxDynamicSharedMemorySize, GEMM_SMEM);
    cudaFuncSetAttribute(attn_kernel,
                         cudaFuncAttributeMaxDynamicSharedMemorySize, ATT_SMEM_BYTES);

    pack_kernel<<<PACK_BLOCKS, 256>>>(q, k, v, Wq, Wk, Wv, Wo);
    qkv_proj_kernel<<<dim3(L / BMM, DM / BMM, 3), 256, GEMM_SMEM>>>(bq, bk, bv);
    attn_kernel<<<dim3(L / 64, NH), 256, ATT_SMEM_BYTES>>>();
    out_proj_kernel<<<dim3(L / BMM, DM / BMM), 256, GEMM_SMEM>>>(bo, out);
}